// round 12
// baseline (speedup 1.0000x reference)
#include <cuda_runtime.h>
#include <cstdint>
#include <cstddef>

#define EMB_K   1024
#define DIMS    64
#define HW_     4096
#define QELEMS  (16*64*64*64)
#define NCTA    512
#define TPB     256
#define MARGIN  3.0f
#define CAP     4
#define RS      80
#define BCHUNK  128
#define NCHUNK  (EMB_K / BCHUNK)
#define FLUSH_CAP 20

// smem layout (48.5 KB -> 4 CTAs/SM)
#define OFF_A    0                       // 128 x 80 = 10240
#define OFF_B0   10240                   // 10240 (reused as cand-idx after sweep)
#define OFF_B1   20480                   // 10240
#define OFF_CST  30720                   // 256 x 2 x CAP x 8 = 16384
#define OFF_SX   47104                   // 128 float2 = 1024
#define OFF_CNT  48128                   // 128 int
#define OFF_RB   48640                   // 128 f32
#define OFF_RED  49152                   // 128 f32
#define SMEM_TOTAL 49664

__device__ uint4  g_eqt[EMB_K * 4];      // int8 codes, original order (temp)
__device__ uint4  g_embq[EMB_K * 4];     // int8 codes, norm-sorted
__device__ float  g_enorm[EMB_K];        // exact norms, ORIGINAL order (re-rank)
__device__ float  g_setmp[EMB_K];        // scales, original order (temp)
__device__ float2 g_sens[EMB_K];         // sorted (norm, scale)
__device__ int    g_perm[EMB_K];         // sorted pos -> original idx
__device__ float4 g_cstat[NCHUNK];       // (min_norm, 1/max_se, 1/min_se, 0)
__device__ float  g_partial[NCTA];
__device__ unsigned int g_ticket;

__device__ __forceinline__ uint32_t smem_u32(const void* p) {
    uint32_t a;
    asm("{ .reg .u64 t; cvta.to.shared.u64 t, %1; cvt.u32.u64 %0, t; }" : "=r"(a) : "l"(p));
    return a;
}

__device__ __forceinline__ void ldsm4(uint32_t* r, uint32_t addr) {
    asm volatile("ldmatrix.sync.aligned.m8n8.x4.shared.b16 {%0,%1,%2,%3}, [%4];"
                 : "=r"(r[0]), "=r"(r[1]), "=r"(r[2]), "=r"(r[3]) : "r"(addr));
}

__device__ __forceinline__ void imma16832(int* c, const uint32_t* a, const uint32_t* b) {
    asm volatile("mma.sync.aligned.m16n8k32.row.col.s32.s8.s8.s32 "
                 "{%0,%1,%2,%3}, {%4,%5,%6,%7}, {%8,%9}, {%0,%1,%2,%3};"
                 : "+r"(c[0]), "+r"(c[1]), "+r"(c[2]), "+r"(c[3])
                 : "r"(a[0]), "r"(a[1]), "r"(a[2]), "r"(a[3]), "r"(b[0]), "r"(b[1]));
}

__device__ __forceinline__ void cp16(uint32_t saddr, const void* g) {
    asm volatile("cp.async.cg.shared.global [%0], [%1], 16;" :: "r"(saddr), "l"(g));
}

__device__ __forceinline__ void upd(float& best, int& nc, float2* st, float d, int ci) {
    if (d < best + MARGIN) {
        if (d < best) best = d;
        if (nc == CAP) {
            int m = 0;
#pragma unroll
            for (int q = 0; q < CAP; q++) {
                float2 e = st[q];
                if (e.x < best + MARGIN) st[m++] = e;
            }
            nc = m;
        }
        if (nc < CAP) {
            st[nc] = make_float2(d, __int_as_float(ci));
            nc++;
        } else {
            int wq = 0; float wd = st[0].x;
#pragma unroll
            for (int q = 1; q < CAP; q++) { float v = st[q].x; if (v > wd) { wd = v; wq = q; } }
            if (d < wd) st[wq] = make_float2(d, __int_as_float(ci));
        }
    }
}

__device__ __forceinline__ int q8(float v, float inv) {
    int q = __float2int_rn(v * inv);
    return max(-127, min(127, q));
}

// ---- pre1: quantize + norms/scales (original order) ----
__global__ void vq_pre1(const float* __restrict__ emb) {
    int c = blockIdx.x * blockDim.x + threadIdx.x;
    if (c >= EMB_K) return;
    const float4* er = (const float4*)(emb + (size_t)c * DIMS);
    float4 v[16];
    float s = 0.f, am = 0.f;
#pragma unroll
    for (int i = 0; i < 16; i++) {
        v[i] = __ldg(er + i);
        s += v[i].x * v[i].x + v[i].y * v[i].y + v[i].z * v[i].z + v[i].w * v[i].w;
        am = fmaxf(am, fmaxf(fmaxf(fabsf(v[i].x), fabsf(v[i].y)),
                             fmaxf(fabsf(v[i].z), fabsf(v[i].w))));
    }
    float inv = (am > 0.f) ? (127.0f / am) : 0.f;
#pragma unroll
    for (int j = 0; j < 4; j++) {
        uint32_t w[4];
#pragma unroll
        for (int k = 0; k < 4; k++) {
            float4 t = v[j * 4 + k];
            int q0 = q8(t.x, inv), q1 = q8(t.y, inv), q2 = q8(t.z, inv), q3 = q8(t.w, inv);
            w[k] = (uint32_t)(q0 & 0xFF) | ((uint32_t)(q1 & 0xFF) << 8) |
                   ((uint32_t)(q2 & 0xFF) << 16) | ((uint32_t)(q3 & 0xFF) << 24);
        }
        g_eqt[c * 4 + j] = make_uint4(w[0], w[1], w[2], w[3]);
    }
    g_enorm[c] = s;
    g_setmp[c] = am * (1.0f / 127.0f);
}

// ---- pre2: rank by norm (stable) and scatter into sorted layout ----
__global__ void vq_pre2() {
    int c = blockIdx.x * blockDim.x + threadIdx.x;   // 32x32
    if (c >= EMB_K) return;
    float enc = g_enorm[c];
    int rank = 0;
#pragma unroll 4
    for (int j = 0; j < EMB_K; j++) {
        float ej = __ldg(&g_enorm[j]);
        rank += (ej < enc) || (ej == enc && j < c);
    }
#pragma unroll
    for (int k = 0; k < 4; k++) g_embq[rank * 4 + k] = g_eqt[c * 4 + k];
    g_sens[rank] = make_float2(enc, g_setmp[c]);
    g_perm[rank] = c;
}

// ---- pre3: per-chunk stats ----
__global__ void vq_pre3() {
    __shared__ float smn[128], smx[128];
    int ch = blockIdx.x, t = threadIdx.x;            // 8 x 128
    float se = g_sens[ch * BCHUNK + t].y;
    smn[t] = se; smx[t] = se;
    __syncthreads();
    for (int s = 64; s > 0; s >>= 1) {
        if (t < s) {
            smn[t] = fminf(smn[t], smn[t + s]);
            smx[t] = fmaxf(smx[t], smx[t + s]);
        }
        __syncthreads();
    }
    if (t == 0) {
        float mnse = smn[0], mxse = smx[0];
        g_cstat[ch] = make_float4(g_sens[ch * BCHUNK].x,
                                  (mxse > 0.f) ? (1.0f / mxse) : 3.4e38f,
                                  (mnse > 0.f) ? (1.0f / mnse) : 3.4e38f, 0.f);
    }
}

// ---------------- fused main kernel ----------------
__global__ void __launch_bounds__(TPB, 4) vq_main(
    const float* __restrict__ in,
    const float* __restrict__ emb,
    float* __restrict__ out0,
    float* __restrict__ out_q,
    float* __restrict__ out_idx)
{
    extern __shared__ char smem[];
    const uint32_t sb = smem_u32(smem);
    const int t = threadIdx.x;
    const int lane = t & 31;
    const int w = t >> 5;
    const int n0blk = blockIdx.x * 128;
    const int b = n0blk >> 12;
    const int hw0 = n0blk & 4095;

    if (t < 128) ((int*)(smem + OFF_CNT))[t] = 0;

    // ---- A tile: quantize 128 query rows; store (msx, invK) per row ----
    float2* sxa = (float2*)(smem + OFF_SX);
    if (t < 128) {
        const float* xin = in + b * (DIMS * HW_) + hw0 + t;
        float am = 0.f;
#pragma unroll
        for (int k = 0; k < DIMS; k++) am = fmaxf(am, fabsf(__ldg(xin + (size_t)k * HW_)));
        float inv = (am > 0.f) ? (127.0f / am) : 0.f;
        float sx = am * (1.0f / 127.0f);
        sxa[t] = make_float2(-2.0f * sx, (am > 0.f) ? (0.5f / sx) : 3.4e38f);
#pragma unroll
        for (int j = 0; j < 4; j++) {
            uint32_t wv[4];
#pragma unroll
            for (int k = 0; k < 4; k++) {
                int i0 = j * 16 + k * 4;
                int q0 = q8(__ldg(xin + (size_t)(i0 + 0) * HW_), inv);
                int q1 = q8(__ldg(xin + (size_t)(i0 + 1) * HW_), inv);
                int q2 = q8(__ldg(xin + (size_t)(i0 + 2) * HW_), inv);
                int q3 = q8(__ldg(xin + (size_t)(i0 + 3) * HW_), inv);
                wv[k] = (uint32_t)(q0 & 0xFF) | ((uint32_t)(q1 & 0xFF) << 8) |
                        ((uint32_t)(q2 & 0xFF) << 16) | ((uint32_t)(q3 & 0xFF) << 24);
            }
            *(uint4*)(smem + OFF_A + t * RS + j * 16) = make_uint4(wv[0], wv[1], wv[2], wv[3]);
        }
    }

    // prefetch chunk 0 while A settles
    {
        const uint4* src = g_embq;
#pragma unroll
        for (int i = 0; i < 2; i++) {
            int idx = t + i * TPB;
            cp16(sb + OFF_B0 + (idx >> 2) * RS + (idx & 3) * 16, src + idx);
        }
        asm volatile("cp.async.commit_group;" ::: "memory");
    }
    asm volatile("cp.async.wait_group 0;" ::: "memory");
    __syncthreads();

    // ---- A fragments ----
    const int wr0 = w * 16;
    uint32_t a[8];
    {
        uint32_t base = sb + OFF_A + (uint32_t)((wr0 + (lane & 15)) * RS) + (uint32_t)((lane >> 4) * 16);
        ldsm4(a, base);
        ldsm4(a + 4, base + 32);
    }

    const int g4 = lane >> 2, tid4 = lane & 3;
    const float2 s0 = sxa[wr0 + g4];
    const float2 s1 = sxa[wr0 + 8 + g4];
    const float msx0 = s0.x, invK0 = s0.y;
    const float msx1 = s1.x, invK1 = s1.y;
    float best0 = 3.4e38f, best1 = 3.4e38f;
    int nc0 = 0, nc1 = 0;
    float2* st0 = (float2*)(smem + OFF_CST) + (size_t)t * 2 * CAP;
    float2* st1 = st0 + CAP;

    for (int ch = 0; ch < NCHUNK; ch++) {
        if (ch) __syncthreads();                      // prev buf fully consumed
        if (ch + 1 < NCHUNK) {                        // prefetch next
            uint32_t boff = ((ch + 1) & 1) ? OFF_B1 : OFF_B0;
            const uint4* src = g_embq + (ch + 1) * (BCHUNK * 4);
#pragma unroll
            for (int i = 0; i < 2; i++) {
                int idx = t + i * TPB;
                cp16(sb + boff + (idx >> 2) * RS + (idx & 3) * 16, src + idx);
            }
            asm volatile("cp.async.commit_group;" ::: "memory");
            asm volatile("cp.async.wait_group 1;" ::: "memory");
        } else {
            asm volatile("cp.async.wait_group 0;" ::: "memory");
        }
        __syncthreads();

        // per-chunk conservative integer thresholds (per row)
        float4 cs = __ldg(&g_cstat[ch]);
        float bm0 = best0 + MARGIN, bm1 = best1 + MARGIN;
        float n0 = cs.x - bm0, n1 = cs.x - bm1;
        int thr0 = __float2int_rd(n0 * ((n0 > 0.f) ? (invK0 * cs.y) : (invK0 * cs.z)));
        int thr1 = __float2int_rd(n1 * ((n1 > 0.f) ? (invK1 * cs.y) : (invK1 * cs.z)));

        const uint32_t bbase = sb + (((ch & 1) ? OFF_B1 : OFF_B0));
        const int cbase = ch * BCHUNK;
#pragma unroll 2
        for (int nt = 0; nt < BCHUNK / 8; nt++) {
            uint32_t bb[4];
            uint32_t baddr = bbase + (uint32_t)((nt * 8 + (lane & 7)) * RS)
                             + (uint32_t)((lane >> 3) * 16);
            ldsm4(bb, baddr);
            int acc[4] = {0, 0, 0, 0};
            imma16832(acc, a, bb);
            imma16832(acc, a + 4, bb + 2);

            int c0 = cbase + nt * 8 + 2 * tid4;
            if (acc[0] > thr0 || acc[1] > thr0) {     // rare slow path
                float4 ns = __ldg((const float4*)(g_sens + c0));
                float d0 = fmaf((float)acc[0] * ns.y, msx0, ns.x);
                float d1 = fmaf((float)acc[1] * ns.w, msx0, ns.z);
                int o0 = __ldg(&g_perm[c0]), o1 = __ldg(&g_perm[c0 + 1]);
                upd(best0, nc0, st0, d0, o0);
                upd(best0, nc0, st0, d1, o1);
            }
            if (acc[2] > thr1 || acc[3] > thr1) {
                float4 ns = __ldg((const float4*)(g_sens + c0));
                float d2 = fmaf((float)acc[2] * ns.y, msx1, ns.x);
                float d3 = fmaf((float)acc[3] * ns.w, msx1, ns.z);
                int o0 = __ldg(&g_perm[c0]), o1 = __ldg(&g_perm[c0 + 1]);
                upd(best1, nc1, st1, d2, o0);
                upd(best1, nc1, st1, d3, o1);
            }
        }

        // share best within the quad serving each row (tightens next threshold)
        best0 = fminf(best0, __shfl_xor_sync(0xffffffffu, best0, 1));
        best0 = fminf(best0, __shfl_xor_sync(0xffffffffu, best0, 2));
        best1 = fminf(best1, __shfl_xor_sync(0xffffffffu, best1, 1));
        best1 = fminf(best1, __shfl_xor_sync(0xffffffffu, best1, 2));
    }

    float* rb = (float*)(smem + OFF_RB);
    if (tid4 == 0) { rb[wr0 + g4] = best0; rb[wr0 + 8 + g4] = best1; }
    __syncthreads();

    // ---- flush candidates within margin of row-global best ----
    int* cnt = (int*)(smem + OFF_CNT);
    int* cix = (int*)(smem + OFF_B0);
    {
        float th0 = rb[wr0 + g4] + MARGIN;
        float th1 = rb[wr0 + 8 + g4] + MARGIN;
        for (int q = 0; q < nc0; q++) {
            float2 e = st0[q];
            if (e.x < th0) {
                int p = atomicAdd(&cnt[wr0 + g4], 1);
                if (p < FLUSH_CAP) cix[(wr0 + g4) * FLUSH_CAP + p] = __float_as_int(e.y);
            }
        }
        for (int q = 0; q < nc1; q++) {
            float2 e = st1[q];
            if (e.x < th1) {
                int p = atomicAdd(&cnt[wr0 + 8 + g4], 1);
                if (p < FLUSH_CAP) cix[(wr0 + 8 + g4) * FLUSH_CAP + p] = __float_as_int(e.y);
            }
        }
    }
    __syncthreads();

    // ---- exact fp32 re-rank + outputs (original-index domain) ----
    float* red = (float*)(smem + OFF_RED);
    if (t < 128) {
        const float* xin = in + b * (DIMS * HW_) + hw0 + t;
        int m = cnt[t]; if (m > FLUSH_CAP) m = FLUSH_CAP;
        float bd = 3.4e38f; int bi = 0x7fffffff;
        for (int q = 0; q < m; q++) {
            int ci = cix[t * FLUSH_CAP + q];
            const float4* er = (const float4*)(emb + (size_t)ci * DIMS);
            float dot = 0.f;
#pragma unroll
            for (int i = 0; i < 16; i++) {
                float4 v = __ldg(er + i);
                dot = fmaf(v.x, __ldg(xin + (size_t)(4 * i + 0) * HW_), dot);
                dot = fmaf(v.y, __ldg(xin + (size_t)(4 * i + 1) * HW_), dot);
                dot = fmaf(v.z, __ldg(xin + (size_t)(4 * i + 2) * HW_), dot);
                dot = fmaf(v.w, __ldg(xin + (size_t)(4 * i + 3) * HW_), dot);
            }
            float ed = fmaf(-2.f, dot, __ldg(&g_enorm[ci]));
            if (ed < bd || (ed == bd && ci < bi)) { bd = ed; bi = ci; }
        }

        int n = n0blk + t;
        out_idx[n] = (float)bi;
        float* oq = out_q + b * (DIMS * HW_) + hw0 + t;
        const float4* er = (const float4*)(emb + (size_t)bi * DIMS);
        float loss = 0.f;
#pragma unroll
        for (int i = 0; i < 16; i++) {
            float4 v = __ldg(er + i);
            int k = i * 4;
            float x0 = __ldg(xin + (size_t)(k + 0) * HW_);
            float x1 = __ldg(xin + (size_t)(k + 1) * HW_);
            float x2 = __ldg(xin + (size_t)(k + 2) * HW_);
            float x3 = __ldg(xin + (size_t)(k + 3) * HW_);
            float d0 = v.x - x0, d1 = v.y - x1, d2 = v.z - x2, d3 = v.w - x3;
            loss += d0 * d0 + d1 * d1 + d2 * d2 + d3 * d3;
            oq[(size_t)(k + 0) * HW_] = v.x;
            oq[(size_t)(k + 1) * HW_] = v.y;
            oq[(size_t)(k + 2) * HW_] = v.z;
            oq[(size_t)(k + 3) * HW_] = v.w;
        }
        red[t] = loss;
    }
    __syncthreads();
#pragma unroll 1
    for (int s = 64; s > 0; s >>= 1) {
        if (t < s) red[t] += red[t + s];
        __syncthreads();
    }

    // ---- fused finalize ----
    __shared__ int slast;
    if (t == 0) {
        g_partial[blockIdx.x] = red[0];
        __threadfence();
        unsigned int old = atomicInc(&g_ticket, NCTA - 1);
        slast = (old == NCTA - 1);
    }
    __syncthreads();
    if (slast && t < 32) {
        __threadfence();
        float s = 0.f;
#pragma unroll
        for (int i = 0; i < NCTA / 32; i++) s += g_partial[t + 32 * i];
#pragma unroll
        for (int o = 16; o > 0; o >>= 1) s += __shfl_down_sync(0xffffffffu, s, o);
        if (t == 0) out0[0] = 0.25f * s * (1.0f / (float)QELEMS);
    }
}

extern "C" void kernel_launch(void* const* d_in, const int* in_sizes, int n_in,
                              void* d_out, int out_size) {
    const float* in  = (const float*)d_in[0];
    const float* emb = (const float*)d_in[1];
    if (n_in >= 2 && in_sizes[0] == EMB_K * DIMS && in_sizes[1] == QELEMS) {
        const float* tmp = in; in = emb; emb = tmp;
    }
    float* out = (float*)d_out;
    float* out_q   = out + 1;
    float* out_idx = out + 1 + QELEMS;

    static bool attr_done = false;
    if (!attr_done) {
        cudaFuncSetAttribute(vq_main, cudaFuncAttributeMaxDynamicSharedMemorySize, SMEM_TOTAL);
        attr_done = true;
    }

    vq_pre1<<<32, 32>>>(emb);
    vq_pre2<<<32, 32>>>();
    vq_pre3<<<NCHUNK, 128>>>();
    vq_main<<<NCTA, TPB, SMEM_TOTAL>>>(in, emb, out, out_q, out_idx);
}

// round 14
// speedup vs baseline: 1.0979x; 1.0979x over previous
#include <cuda_runtime.h>
#include <cstdint>
#include <cstddef>

#define EMB_K   1024
#define DIMS    64
#define HW_     4096
#define QELEMS  (16*64*64*64)
#define NCTA    1024
#define TPB     128
#define ROWS    64            // query rows per CTA
#define MARGIN  3.0f
#define CAP     4
#define RS      80            // smem row stride (bytes) for 64B int8 rows
#define BCHUNK  128
#define NCHUNK  (EMB_K / BCHUNK)
#define FLUSH_CAP 20

// smem layout: 33 KB -> 6 CTAs/SM (24 warps), balanced 1024-CTA grid
#define OFF_A    0                       // 64 x 80 = 5120
#define OFF_B    5120                    // 128 x 80 = 10240 (reused as cand-idx)
#define OFF_ENS  15360                   // 1024 float2 = 8192
#define OFF_SX   23552                   // 64 float2 = 512
#define OFF_CST  24064                   // 128 thr x 2 x CAP x 8 = 8192
#define OFF_CNT  32256                   // 64 int
#define OFF_RB   32512                   // 64 f32
#define OFF_RED  32768                   // 64 f32
#define SMEM_TOTAL 33024

__device__ uint4 g_embq[EMB_K * 4];      // int8 codes, 64B/row
__device__ float g_enorm[EMB_K];
__device__ float g_escale[EMB_K];
__device__ float g_partial[NCTA];
__device__ unsigned int g_ticket;

__device__ __forceinline__ uint32_t smem_u32(const void* p) {
    uint32_t a;
    asm("{ .reg .u64 t; cvta.to.shared.u64 t, %1; cvt.u32.u64 %0, t; }" : "=r"(a) : "l"(p));
    return a;
}

__device__ __forceinline__ void ldsm4(uint32_t* r, uint32_t addr) {
    asm volatile("ldmatrix.sync.aligned.m8n8.x4.shared.b16 {%0,%1,%2,%3}, [%4];"
                 : "=r"(r[0]), "=r"(r[1]), "=r"(r[2]), "=r"(r[3]) : "r"(addr));
}

__device__ __forceinline__ void imma16832(int* c, const uint32_t* a, const uint32_t* b) {
    asm volatile("mma.sync.aligned.m16n8k32.row.col.s32.s8.s8.s32 "
                 "{%0,%1,%2,%3}, {%4,%5,%6,%7}, {%8,%9}, {%0,%1,%2,%3};"
                 : "+r"(c[0]), "+r"(c[1]), "+r"(c[2]), "+r"(c[3])
                 : "r"(a[0]), "r"(a[1]), "r"(a[2]), "r"(a[3]), "r"(b[0]), "r"(b[1]));
}

__device__ __forceinline__ void upd(float& best, int& nc, float2* st, float d, int ci) {
    if (d < best + MARGIN) {
        if (d < best) best = d;
        if (nc == CAP) {
            int m = 0;
#pragma unroll
            for (int q = 0; q < CAP; q++) {
                float2 e = st[q];
                if (e.x < best + MARGIN) st[m++] = e;
            }
            nc = m;
        }
        if (nc < CAP) {
            st[nc] = make_float2(d, __int_as_float(ci));
            nc++;
        } else {
            int wq = 0; float wd = st[0].x;
#pragma unroll
            for (int q = 1; q < CAP; q++) { float v = st[q].x; if (v > wd) { wd = v; wq = q; } }
            if (d < wd) st[wq] = make_float2(d, __int_as_float(ci));
        }
    }
}

__device__ __forceinline__ int q8(float v, float inv) {
    int q = __float2int_rn(v * inv);
    return max(-127, min(127, q));
}

// ---------------- precompute: int8 table + scales + exact fp32 norms ----------------
__global__ void vq_pre(const float* __restrict__ emb) {
    int c = blockIdx.x * blockDim.x + threadIdx.x;
    if (c >= EMB_K) return;
    const float4* er = (const float4*)(emb + (size_t)c * DIMS);
    float4 v[16];
    float s = 0.f, am = 0.f;
#pragma unroll
    for (int i = 0; i < 16; i++) {
        v[i] = __ldg(er + i);
        s += v[i].x * v[i].x + v[i].y * v[i].y + v[i].z * v[i].z + v[i].w * v[i].w;
        am = fmaxf(am, fmaxf(fmaxf(fabsf(v[i].x), fabsf(v[i].y)),
                             fmaxf(fabsf(v[i].z), fabsf(v[i].w))));
    }
    float se  = am * (1.0f / 127.0f);
    float inv = (am > 0.f) ? (127.0f / am) : 0.f;
#pragma unroll
    for (int j = 0; j < 4; j++) {
        uint32_t w[4];
#pragma unroll
        for (int k = 0; k < 4; k++) {
            float4 t = v[j * 4 + k];
            int q0 = q8(t.x, inv), q1 = q8(t.y, inv), q2 = q8(t.z, inv), q3 = q8(t.w, inv);
            w[k] = (uint32_t)(q0 & 0xFF) | ((uint32_t)(q1 & 0xFF) << 8) |
                   ((uint32_t)(q2 & 0xFF) << 16) | ((uint32_t)(q3 & 0xFF) << 24);
        }
        g_embq[c * 4 + j] = make_uint4(w[0], w[1], w[2], w[3]);
    }
    g_enorm[c] = s;
    g_escale[c] = se;
}

// ---------------- fused main kernel ----------------
__global__ void __launch_bounds__(TPB, 6) vq_main(
    const float* __restrict__ in,
    const float* __restrict__ emb,
    float* __restrict__ out0,
    float* __restrict__ out_q,
    float* __restrict__ out_idx)
{
    extern __shared__ char smem[];
    const uint32_t sb = smem_u32(smem);
    const int t = threadIdx.x;
    const int lane = t & 31;
    const int w = t >> 5;
    const int n0blk = blockIdx.x * ROWS;
    const int b = n0blk >> 12;
    const int hw0 = n0blk & 4095;

    float2* ens = (float2*)(smem + OFF_ENS);
#pragma unroll
    for (int i = 0; i < 8; i++) {
        int c = t + i * TPB;
        ens[c] = make_float2(g_enorm[c], g_escale[c]);
    }
    if (t < ROWS) ((int*)(smem + OFF_CNT))[t] = 0;

    // ---- A tile: quantize 64 query rows ----
    float2* sxa = (float2*)(smem + OFF_SX);
    if (t < ROWS) {
        const float* xin = in + b * (DIMS * HW_) + hw0 + t;
        float am = 0.f;
#pragma unroll
        for (int k = 0; k < DIMS; k++) am = fmaxf(am, fabsf(__ldg(xin + (size_t)k * HW_)));
        float inv = (am > 0.f) ? (127.0f / am) : 0.f;
        float sx = am * (1.0f / 127.0f);
        sxa[t] = make_float2(-2.0f * sx, 0.f);
#pragma unroll
        for (int j = 0; j < 4; j++) {
            uint32_t wv[4];
#pragma unroll
            for (int k = 0; k < 4; k++) {
                int i0 = j * 16 + k * 4;
                int q0 = q8(__ldg(xin + (size_t)(i0 + 0) * HW_), inv);
                int q1 = q8(__ldg(xin + (size_t)(i0 + 1) * HW_), inv);
                int q2 = q8(__ldg(xin + (size_t)(i0 + 2) * HW_), inv);
                int q3 = q8(__ldg(xin + (size_t)(i0 + 3) * HW_), inv);
                wv[k] = (uint32_t)(q0 & 0xFF) | ((uint32_t)(q1 & 0xFF) << 8) |
                        ((uint32_t)(q2 & 0xFF) << 16) | ((uint32_t)(q3 & 0xFF) << 24);
            }
            *(uint4*)(smem + OFF_A + t * RS + j * 16) = make_uint4(wv[0], wv[1], wv[2], wv[3]);
        }
    }
    __syncthreads();

    // ---- A fragments: 8 regs, 16 rows x 64 int8 per warp ----
    const int wr0 = w * 16;
    uint32_t a[8];
    {
        uint32_t base = sb + OFF_A + (uint32_t)((wr0 + (lane & 15)) * RS) + (uint32_t)((lane >> 4) * 16);
        ldsm4(a, base);          // k 0..31
        ldsm4(a + 4, base + 32); // k 32..63
    }

    const int g4 = lane >> 2, tid4 = lane & 3;
    const float msx0 = sxa[wr0 + g4].x;
    const float msx1 = sxa[wr0 + 8 + g4].x;
    float best0 = 3.4e38f, best1 = 3.4e38f;
    int nc0 = 0, nc1 = 0;
    float2* st0 = (float2*)(smem + OFF_CST) + (size_t)t * 2 * CAP;
    float2* st1 = st0 + CAP;

    for (int ch = 0; ch < NCHUNK; ch++) {
        if (ch) __syncthreads();
        // stage B chunk: 128 codes x 64B (coalesced LDG.128)
        const uint4* src = g_embq + ch * (BCHUNK * 4);
#pragma unroll
        for (int i = 0; i < 4; i++) {
            int idx = t + i * TPB;                     // 0..511
            uint4 v = __ldg(src + idx);
            *(uint4*)(smem + OFF_B + (idx >> 2) * RS + (idx & 3) * 16) = v;
        }
        __syncthreads();

        const int cbase = ch * BCHUNK;
#pragma unroll 2
        for (int nt = 0; nt < BCHUNK / 8; nt++) {
            uint32_t bb[4];
            uint32_t baddr = sb + OFF_B + (uint32_t)((nt * 8 + (lane & 7)) * RS)
                             + (uint32_t)((lane >> 3) * 16);
            ldsm4(bb, baddr);
            int acc[4] = {0, 0, 0, 0};
            imma16832(acc, a, bb);          // serial chain (no extra IADDs)
            imma16832(acc, a + 4, bb + 2);

            int c0 = cbase + nt * 8 + 2 * tid4;
            float4 es = *(const float4*)&ens[c0];      // en0, se0, en1, se1
            float d0 = fmaf((float)acc[0], msx0 * es.y, es.x);
            float d1 = fmaf((float)acc[1], msx0 * es.w, es.z);
            float d2 = fmaf((float)acc[2], msx1 * es.y, es.x);
            float d3 = fmaf((float)acc[3], msx1 * es.w, es.z);
            if (fminf(d0, d1) < best0 + MARGIN) {      // rare path
                upd(best0, nc0, st0, d0, c0);
                upd(best0, nc0, st0, d1, c0 + 1);
            }
            if (fminf(d2, d3) < best1 + MARGIN) {
                upd(best1, nc1, st1, d2, c0);
                upd(best1, nc1, st1, d3, c0 + 1);
            }
        }
    }

    // ---- row-global coarse minima ----
#pragma unroll
    for (int o = 1; o <= 2; o <<= 1) {
        best0 = fminf(best0, __shfl_xor_sync(0xffffffffu, best0, o));
        best1 = fminf(best1, __shfl_xor_sync(0xffffffffu, best1, o));
    }
    float* rb = (float*)(smem + OFF_RB);
    if (tid4 == 0) { rb[wr0 + g4] = best0; rb[wr0 + 8 + g4] = best1; }
    __syncthreads();

    // ---- flush candidates within margin of row-global best ----
    int* cnt = (int*)(smem + OFF_CNT);
    int* cix = (int*)(smem + OFF_B);             // reused: 64 rows x FLUSH_CAP
    {
        float th0 = rb[wr0 + g4] + MARGIN;
        float th1 = rb[wr0 + 8 + g4] + MARGIN;
        for (int q = 0; q < nc0; q++) {
            float2 e = st0[q];
            if (e.x < th0) {
                int p = atomicAdd(&cnt[wr0 + g4], 1);
                if (p < FLUSH_CAP) cix[(wr0 + g4) * FLUSH_CAP + p] = __float_as_int(e.y);
            }
        }
        for (int q = 0; q < nc1; q++) {
            float2 e = st1[q];
            if (e.x < th1) {
                int p = atomicAdd(&cnt[wr0 + 8 + g4], 1);
                if (p < FLUSH_CAP) cix[(wr0 + 8 + g4) * FLUSH_CAP + p] = __float_as_int(e.y);
            }
        }
    }
    __syncthreads();

    // ---- exact fp32 re-rank + outputs ----
    float* red = (float*)(smem + OFF_RED);
    if (t < ROWS) {
        const float* xin = in + b * (DIMS * HW_) + hw0 + t;
        int m = cnt[t]; if (m > FLUSH_CAP) m = FLUSH_CAP;
        float bd = 3.4e38f; int bi = 0x7fffffff;
        for (int q = 0; q < m; q++) {
            int ci = cix[t * FLUSH_CAP + q];
            const float4* er = (const float4*)(emb + (size_t)ci * DIMS);
            float dot = 0.f;
#pragma unroll
            for (int i = 0; i < 16; i++) {
                float4 v = __ldg(er + i);
                dot = fmaf(v.x, __ldg(xin + (size_t)(4 * i + 0) * HW_), dot);
                dot = fmaf(v.y, __ldg(xin + (size_t)(4 * i + 1) * HW_), dot);
                dot = fmaf(v.z, __ldg(xin + (size_t)(4 * i + 2) * HW_), dot);
                dot = fmaf(v.w, __ldg(xin + (size_t)(4 * i + 3) * HW_), dot);
            }
            float ed = fmaf(-2.f, dot, ens[ci].x);
            if (ed < bd || (ed == bd && ci < bi)) { bd = ed; bi = ci; }
        }

        int n = n0blk + t;
        out_idx[n] = (float)bi;
        float* oq = out_q + b * (DIMS * HW_) + hw0 + t;
        const float4* er = (const float4*)(emb + (size_t)bi * DIMS);
        float loss = 0.f;
#pragma unroll
        for (int i = 0; i < 16; i++) {
            float4 v = __ldg(er + i);
            int k = i * 4;
            float x0 = __ldg(xin + (size_t)(k + 0) * HW_);
            float x1 = __ldg(xin + (size_t)(k + 1) * HW_);
            float x2 = __ldg(xin + (size_t)(k + 2) * HW_);
            float x3 = __ldg(xin + (size_t)(k + 3) * HW_);
            float d0 = v.x - x0, d1 = v.y - x1, d2 = v.z - x2, d3 = v.w - x3;
            loss += d0 * d0 + d1 * d1 + d2 * d2 + d3 * d3;
            oq[(size_t)(k + 0) * HW_] = v.x;
            oq[(size_t)(k + 1) * HW_] = v.y;
            oq[(size_t)(k + 2) * HW_] = v.z;
            oq[(size_t)(k + 3) * HW_] = v.w;
        }
        red[t] = loss;
    }
    __syncthreads();
#pragma unroll 1
    for (int s = 32; s > 0; s >>= 1) {
        if (t < s) red[t] += red[t + s];
        __syncthreads();
    }

    // ---- fused finalize: last CTA reduces partials deterministically ----
    __shared__ int slast;
    if (t == 0) {
        g_partial[blockIdx.x] = red[0];
        __threadfence();
        unsigned int old = atomicInc(&g_ticket, NCTA - 1);
        slast = (old == NCTA - 1);
    }
    __syncthreads();
    if (slast && t < 32) {
        __threadfence();
        float s = 0.f;
#pragma unroll
        for (int i = 0; i < NCTA / 32; i++) s += g_partial[t + 32 * i];
#pragma unroll
        for (int o = 16; o > 0; o >>= 1) s += __shfl_down_sync(0xffffffffu, s, o);
        if (t == 0) out0[0] = 0.25f * s * (1.0f / (float)QELEMS);
    }
}

extern "C" void kernel_launch(void* const* d_in, const int* in_sizes, int n_in,
                              void* d_out, int out_size) {
    const float* in  = (const float*)d_in[0];
    const float* emb = (const float*)d_in[1];
    if (n_in >= 2 && in_sizes[0] == EMB_K * DIMS && in_sizes[1] == QELEMS) {
        const float* tmp = in; in = emb; emb = tmp;
    }
    float* out = (float*)d_out;
    float* out_q   = out + 1;
    float* out_idx = out + 1 + QELEMS;

    static bool attr_done = false;
    if (!attr_done) {
        cudaFuncSetAttribute(vq_main, cudaFuncAttributeMaxDynamicSharedMemorySize, SMEM_TOTAL);
        attr_done = true;
    }

    vq_pre<<<32, 32>>>(emb);
    vq_main<<<NCTA, TPB, SMEM_TOTAL>>>(in, emb, out, out_q, out_idx);
}